// round 12
// baseline (speedup 1.0000x reference)
#include <cuda_runtime.h>
#include <cuda_bf16.h>

#define N_CTRL 64
#define N_EVAL 2001
#define DEG 3
#define INV_INTERNAL (1.0f / 61.0f)   // internal knots at k/61

#define TPB 256
#define U_TILE 8
#define VSPLIT 4
#define VCHUNK 501                    // ceil(2001/4)
#define KITER 2                       // ceil(VCHUNK / TPB)
#define NCACHE 8                      // cached cp rows per block

__device__ __forceinline__ float knotf(int j) {
    if (j <= DEG) return 0.0f;
    if (j >= N_CTRL) return 1.0f;
    return (float)(j - DEG) * INV_INTERNAL;
}

// span = clip(searchsorted(knots, t, 'right') - 1, p, n_ctrl-1), analytic
__device__ __forceinline__ int find_span(float t) {
    int k = (int)floorf(t * 61.0f);
    if (k < 0) k = 0;
    if (k > 60) k = 60;
    if (k < 60 && (float)(k + 1) * INV_INTERNAL <= t) ++k;
    if (k > 0  && (float)k * INV_INTERNAL > t)        --k;
    return DEG + k;
}

// Cox-de-Boor (NURBS book A2.2), p=3. FAST=1 uses __fdividef.
template <int FAST>
__device__ __forceinline__ void basis_funcs(float u, int span, float N[4]) {
    float left[4], right[4];
    N[0] = 1.0f;
    #pragma unroll
    for (int j = 1; j <= DEG; ++j) {
        left[j]  = u - knotf(span + 1 - j);
        right[j] = knotf(span + j) - u;
        float saved = 0.0f;
        #pragma unroll
        for (int r = 0; r < j; ++r) {
            float denom = right[r + 1] + left[j - r];
            float temp  = FAST ? __fdividef(N[r], denom) : (N[r] / denom);
            N[r] = saved + right[r + 1] * temp;
            saved = left[j - r] * temp;
        }
        N[j] = saved;
    }
}

// v-basis: closed-form uniform cubic for interior spans; Cox-de-Boor fallback
// at the clamped ends.
__device__ __forceinline__ void basis_v(float v, int span, float B[4]) {
    if (span >= 5 && span <= 61) {
        float t  = v * 61.0f - (float)(span - DEG);   // in [0,1)
        float s  = 1.0f - t;
        float t2 = t * t;
        float t3 = t2 * t;
        B[0] = s * s * s * (1.0f / 6.0f);
        B[3] = t3 * (1.0f / 6.0f);
        B[1] = 0.5f * t3 - t2 + (2.0f / 3.0f);
        B[2] = 1.0f - B[0] - B[1] - B[3];             // partition of unity
    } else {
        basis_funcs<1>(v, span, B);
    }
}

// ---------------- single fused kernel ----------------
__global__ __launch_bounds__(TPB) void nurbs_kernel(const float* __restrict__ cp,
                                                    const float* __restrict__ pu,
                                                    const float* __restrict__ pv,
                                                    float* __restrict__ out) {
    __shared__ float4 s_curve[U_TILE][N_CTRL];      // 8 KB collapsed curves
    __shared__ float  s_cp[NCACHE * N_CTRL * 3];    // 6 KB cached cp rows
    __shared__ int    s_span[U_TILE];
    __shared__ int    s_lo;

    const int u0  = blockIdx.y * U_TILE;
    const int tid = threadIdx.x;
    const int nrows  = (N_EVAL - u0) < U_TILE ? (N_EVAL - u0) : U_TILE;
    const int vstart = blockIdx.x * VCHUNK;
    const int vend   = (vstart + VCHUNK) < N_EVAL ? (vstart + VCHUNK) : N_EVAL;

    // ---- phase 0: spans for the 8 rows ----
    if (tid < U_TILE) {
        int uu = u0 + tid;
        if (uu > N_EVAL - 1) uu = N_EVAL - 1;
        s_span[tid] = find_span(pu[uu]);
    }
    __syncthreads();

    // row window to cache: [lo, lo+NCACHE)
    if (tid == 0) {
        int smin = s_span[0];
        #pragma unroll
        for (int r = 1; r < U_TILE; ++r) smin = s_span[r] < smin ? s_span[r] : smin;
        s_lo = smin - DEG;                              // >= 0
    }
    __syncthreads();
    const int lo = s_lo;

    // ---- phase 1: coalesced float4 cache of cp rows lo..lo+7 (clamped) ----
    {
        int rows_avail = N_CTRL - lo;                   // <= 64
        int nrow_c = rows_avail < NCACHE ? rows_avail : NCACHE;
        int nf4 = nrow_c * (N_CTRL * 3 / 4);            // 48 float4 per row
        const float4* src = (const float4*)(cp + lo * (N_CTRL * 3));
        float4* dst = (float4*)s_cp;
        for (int i = tid; i < nf4; i += TPB) dst[i] = src[i];
    }
    __syncthreads();

    // ---- phase 2: u-collapse from smem; 512 items, 2 per thread ----
    #pragma unroll
    for (int it = 0; it < 2; ++it) {
        const int item = tid + it * TPB;
        const int r = item >> 6;      // 0..7
        const int j = item & 63;      // 0..63
        if (r < nrows) {
            const float uu = pu[u0 + r];                // L1-hot broadcast
            const int   su = s_span[r];
            float B[4];
            basis_funcs<0>(uu, su, B);                  // exact division
            float cx = 0.f, cy = 0.f, cz = 0.f;
            #pragma unroll
            for (int a = 0; a < 4; ++a) {
                const int ri = su - DEG + a;
                const unsigned t = (unsigned)(ri - lo);
                const float* q = (t < NCACHE)
                    ? (s_cp + (t * N_CTRL + j) * 3)
                    : (cp + (ri * N_CTRL + j) * 3);     // fallback (never for linspace)
                cx += B[a] * q[0];
                cy += B[a] * q[1];
                cz += B[a] * q[2];
            }
            s_curve[r][j] = make_float4(cx, cy, cz, 0.f);
        }
    }
    __syncthreads();

    // ---- batched pv loads: independent LDGs in flight ----
    float pvv[KITER];
    #pragma unroll
    for (int k = 0; k < KITER; ++k) {
        int p  = vstart + k * TPB + tid;
        int pc = p < vend ? p : vend - 1;
        pvv[k] = pv[pc];
    }

    // ---- main: closed-form v-basis, 8 rows per point, direct stores ----
    #pragma unroll
    for (int k = 0; k < KITER; ++k) {
        const int p = vstart + k * TPB + tid;
        if (p < vend) {
            const int sv = find_span(pvv[k]);
            float B[4];
            basis_v(pvv[k], sv, B);
            const int o = sv - DEG;
            #pragma unroll
            for (int r = 0; r < U_TILE; ++r) {
                if (r < nrows) {
                    const float4 c0 = s_curve[r][o + 0];
                    const float4 c1 = s_curve[r][o + 1];
                    const float4 c2 = s_curve[r][o + 2];
                    const float4 c3 = s_curve[r][o + 3];
                    float x = B[0] * c0.x + B[1] * c1.x + B[2] * c2.x + B[3] * c3.x;
                    float y = B[0] * c0.y + B[1] * c1.y + B[2] * c2.y + B[3] * c3.y;
                    float z = B[0] * c0.z + B[1] * c1.z + B[2] * c2.z + B[3] * c3.z;
                    float* dst = out + ((size_t)(u0 + r) * N_EVAL + p) * 3;
                    dst[0] = x;
                    dst[1] = y;
                    dst[2] = z;
                }
            }
        }
    }
}

extern "C" void kernel_launch(void* const* d_in, const int* in_sizes, int n_in,
                              void* d_out, int out_size) {
    const float* cp = (const float*)d_in[0];   // [64,64,3]
    const float* pu = (const float*)d_in[1];   // [2001]
    const float* pv = (const float*)d_in[2];   // [2001]
    float* out = (float*)d_out;

    dim3 grid(VSPLIT, (N_EVAL + U_TILE - 1) / U_TILE);   // (4, 251)
    nurbs_kernel<<<grid, TPB>>>(cp, pu, pv, out);
}

// round 13
// speedup vs baseline: 1.1552x; 1.1552x over previous
#include <cuda_runtime.h>
#include <cuda_bf16.h>

#define N_CTRL 64
#define N_EVAL 2001
#define DEG 3
#define INV_INTERNAL (1.0f / 61.0f)   // internal knots at k/61

#define TPB 256
#define U_TILE 8
#define VSPLIT 4
#define VCHUNK 501                    // ceil(2001/4)
#define KITER 2                       // ceil(VCHUNK / TPB)
#define ROWF (N_CTRL * 3)             // 192 floats per cp row
#define WIN 8                         // cached cp rows per block

__device__ __forceinline__ float knotf(int j) {
    if (j <= DEG) return 0.0f;
    if (j >= N_CTRL) return 1.0f;
    return (float)(j - DEG) * INV_INTERNAL;
}

// span = clip(searchsorted(knots, t, 'right') - 1, p, n_ctrl-1), analytic
__device__ __forceinline__ int find_span(float t) {
    int k = (int)floorf(t * 61.0f);
    if (k < 0) k = 0;
    if (k > 60) k = 60;
    if (k < 60 && (float)(k + 1) * INV_INTERNAL <= t) ++k;
    if (k > 0  && (float)k * INV_INTERNAL > t)        --k;
    return DEG + k;
}

// Cox-de-Boor (NURBS book A2.2), p=3, fast division (rel err ~5e-7/weight)
__device__ __forceinline__ void basis_funcs_fast(float u, int span, float N[4]) {
    float left[4], right[4];
    N[0] = 1.0f;
    #pragma unroll
    for (int j = 1; j <= DEG; ++j) {
        left[j]  = u - knotf(span + 1 - j);
        right[j] = knotf(span + j) - u;
        float saved = 0.0f;
        #pragma unroll
        for (int r = 0; r < j; ++r) {
            float temp = __fdividef(N[r], right[r + 1] + left[j - r]);
            N[r] = saved + right[r + 1] * temp;
            saved = left[j - r] * temp;
        }
        N[j] = saved;
    }
}

// v-basis: closed-form uniform cubic for interior spans; Cox-de-Boor fallback
// at the clamped ends.
__device__ __forceinline__ void basis_v(float v, int span, float B[4]) {
    if (span >= 5 && span <= 61) {
        float t  = v * 61.0f - (float)(span - DEG);   // in [0,1)
        float s  = 1.0f - t;
        float t2 = t * t;
        float t3 = t2 * t;
        B[0] = s * s * s * (1.0f / 6.0f);
        B[3] = t3 * (1.0f / 6.0f);
        B[1] = 0.5f * t3 - t2 + (2.0f / 3.0f);
        B[2] = 1.0f - B[0] - B[1] - B[3];             // partition of unity
    } else {
        basis_funcs_fast(v, span, B);
    }
}

// ---------------- single fused kernel ----------------
__global__ __launch_bounds__(TPB) void nurbs_kernel(const float* __restrict__ cp,
                                                    const float* __restrict__ pu,
                                                    const float* __restrict__ pv,
                                                    float* __restrict__ out) {
    __shared__ float4 s_curve[U_TILE][N_CTRL];   // 8 KB collapsed curves
    __shared__ float  s_cp[WIN * ROWF];          // 6 KB cached cp window

    const int u0  = blockIdx.y * U_TILE;
    const int tid = threadIdx.x;
    const int nrows  = (N_EVAL - u0) < U_TILE ? (N_EVAL - u0) : U_TILE;
    const int vstart = blockIdx.x * VCHUNK;
    const int vend   = (vstart + VCHUNK) < N_EVAL ? (vstart + VCHUNK) : N_EVAL;

    // ---- window base: computed redundantly by every thread (no phase) ----
    // Spans of u0..u0+7 lie in {s0, s0+1}; rows [lo, lo+8) cover all reads.
    const int s0 = find_span(pu[u0]);            // broadcast LDG
    int lo = s0 - DEG;
    if (lo > N_CTRL - WIN) lo = N_CTRL - WIN;    // clamp to [0, 56]

    // ---- coalesced cache of 8 cp rows: 384 float4 ----
    {
        const float4* src = (const float4*)(cp + lo * ROWF);
        float4* dst = (float4*)s_cp;
        #pragma unroll
        for (int i = 0; i < 2; ++i) {
            int idx = tid + i * TPB;
            if (idx < (WIN * ROWF) / 4) dst[idx] = src[idx];
        }
    }
    __syncthreads();

    // ---- u-collapse from smem; 512 items, 2 per thread ----
    #pragma unroll
    for (int it = 0; it < 2; ++it) {
        const int item = tid + it * TPB;
        const int r = item >> 6;      // 0..7
        const int j = item & 63;      // 0..63
        if (r < nrows) {
            const float uu = pu[u0 + r];          // broadcast within 64-group
            const int   su = find_span(uu);
            float B[4];
            basis_funcs_fast(uu, su, B);
            const int bt = su - DEG - lo;         // window offset of first row
            float cx = 0.f, cy = 0.f, cz = 0.f;
            if (bt >= 0 && bt + 3 < WIN) {        // warp-uniform: pure LDS path
                const float* q0 = s_cp + bt * ROWF + j * 3;
                #pragma unroll
                for (int a = 0; a < 4; ++a) {
                    const float* q = q0 + a * ROWF;
                    cx += B[a] * q[0];
                    cy += B[a] * q[1];
                    cz += B[a] * q[2];
                }
            } else {                              // robust fallback (not taken
                const float* g0 = cp + (su - DEG) * ROWF + j * 3;   // for linspace)
                #pragma unroll
                for (int a = 0; a < 4; ++a) {
                    const float* q = g0 + a * ROWF;
                    cx += B[a] * q[0];
                    cy += B[a] * q[1];
                    cz += B[a] * q[2];
                }
            }
            s_curve[r][j] = make_float4(cx, cy, cz, 0.f);
        }
    }
    __syncthreads();

    // ---- batched pv loads: independent LDGs in flight ----
    float pvv[KITER];
    #pragma unroll
    for (int k = 0; k < KITER; ++k) {
        int p  = vstart + k * TPB + tid;
        int pc = p < vend ? p : vend - 1;
        pvv[k] = pv[pc];
    }

    // ---- main: closed-form v-basis, 8 rows per point, direct stores ----
    #pragma unroll
    for (int k = 0; k < KITER; ++k) {
        const int p = vstart + k * TPB + tid;
        if (p < vend) {
            const int sv = find_span(pvv[k]);
            float B[4];
            basis_v(pvv[k], sv, B);
            const int o = sv - DEG;
            #pragma unroll
            for (int r = 0; r < U_TILE; ++r) {
                if (r < nrows) {
                    const float4 c0 = s_curve[r][o + 0];
                    const float4 c1 = s_curve[r][o + 1];
                    const float4 c2 = s_curve[r][o + 2];
                    const float4 c3 = s_curve[r][o + 3];
                    float x = B[0] * c0.x + B[1] * c1.x + B[2] * c2.x + B[3] * c3.x;
                    float y = B[0] * c0.y + B[1] * c1.y + B[2] * c2.y + B[3] * c3.y;
                    float z = B[0] * c0.z + B[1] * c1.z + B[2] * c2.z + B[3] * c3.z;
                    float* dst = out + ((size_t)(u0 + r) * N_EVAL + p) * 3;
                    dst[0] = x;
                    dst[1] = y;
                    dst[2] = z;
                }
            }
        }
    }
}

extern "C" void kernel_launch(void* const* d_in, const int* in_sizes, int n_in,
                              void* d_out, int out_size) {
    const float* cp = (const float*)d_in[0];   // [64,64,3]
    const float* pu = (const float*)d_in[1];   // [2001]
    const float* pv = (const float*)d_in[2];   // [2001]
    float* out = (float*)d_out;

    dim3 grid(VSPLIT, (N_EVAL + U_TILE - 1) / U_TILE);   // (4, 251)
    nurbs_kernel<<<grid, TPB>>>(cp, pu, pv, out);
}